// round 12
// baseline (speedup 1.0000x reference)
#include <cuda_runtime.h>
#include <cstdint>

#define CIN   6
#define COUT  16
#define FS    5
#define HIN   512
#define WIN   512
#define HOUT  508
#define WOUT  508
#define BATCHN 32

// ---- dense weights (fp32), built per launch ----
__device__ float g_Wd[FS * FS * CIN * COUT];

__global__ void build_weights(const float* __restrict__ w3,
                              const float* __restrict__ w4,
                              const float* __restrict__ w44,
                              const float* __restrict__ w6) {
    int idx = blockIdx.x * blockDim.x + threadIdx.x;
    if (idx >= FS * FS * CIN * COUT) return;
    int co = idx % COUT;
    int ci = (idx / COUT) % CIN;
    int kk = idx / (COUT * CIN);
    float v = 0.f;
    if (co < 6) {
        int i = co;
        #pragma unroll
        for (int m = 0; m < 3; ++m)
            if (ci == (i + m) % 6) v = w3[(kk * 3 + m) * 6 + i];
    } else if (co < 12) {
        int k = co - 6;
        #pragma unroll
        for (int m = 0; m < 4; ++m)
            if (ci == (k + m) % 6) v = w4[(kk * 4 + m) * 6 + k];
    } else if (co < 15) {
        int k = co - 12;
        const int off[4] = {0, 1, 3, 4};
        #pragma unroll
        for (int m = 0; m < 4; ++m)
            if (ci == (k + off[m]) % 6) v = w44[(kk * 4 + m) * 3 + k];
    } else {
        v = w6[kk * 6 + ci];
    }
    g_Wd[idx] = v;
}

// ===== mma.sync tf32 conv, 2 rows/warp, K-pair-region smem layout =====
// K map: K0..K2,K4..K6 = ci0..ci5 ; K3 = bias lane (input 1.0, weight bias
// on tap 12) ; K7 = 0. Region tq of s_in holds uint2{K(tq), K(tq+4)} per
// pixel -> staging is contiguous STS.64; B fragment = one LDS.64 (2 wf).
// Region stride padded to 64B mod 128B so tq pairs pack into 2 wavefronts.

#define TW    64
#define RT    16            // 8 warps x 2 rows
#define AROWS (RT + 4)      // 20
#define ACOLS (TW + 4)      // 68

#define REG_ELEMS  (AROWS * ACOLS)        // 1360 uint2
#define REG_STRIDE 1368                    // padded: 1368*8 = 10944 B (64 mod 128)
#define SIN_BYTES  (4 * REG_STRIDE * 8)    // 43776
#define SW_BYTES   (25 * 8 * 4 * 16)       // 12800
#define SMEM_BYTES (SIN_BYTES + SW_BYTES)

#define ONE_TF32 0x3F800000u

__device__ __forceinline__ uint32_t cvt_tf32(float f) {
    uint32_t u;
    asm("cvt.rna.tf32.f32 %0, %1;" : "=r"(u) : "f"(f));
    return u;
}

__device__ __forceinline__ void mma_tf32(float d[4],
                                         uint32_t a0, uint32_t a1,
                                         uint32_t a2, uint32_t a3,
                                         uint32_t b0, uint32_t b1) {
    asm volatile(
        "mma.sync.aligned.m16n8k8.row.col.f32.tf32.tf32.f32 "
        "{%0,%1,%2,%3}, {%4,%5,%6,%7}, {%8,%9}, {%0,%1,%2,%3};"
        : "+f"(d[0]), "+f"(d[1]), "+f"(d[2]), "+f"(d[3])
        : "r"(a0), "r"(a1), "r"(a2), "r"(a3), "r"(b0), "r"(b1));
}

__global__ __launch_bounds__(256, 2) void conv_mma_kernel(
    const float* __restrict__ in,
    const float* __restrict__ bias,
    float* __restrict__ out) {

    extern __shared__ char smem[];
    uint2* s_u2 = (uint2*)smem;                        // 4 regions of REG_STRIDE
    // s_w2[tap][gg][tqq] = uint4{(g,Ktqq),(g,Ktqq+4),(g+8,Ktqq),(g+8,Ktqq+4)}
    uint32_t* s_w2 = (uint32_t*)(smem + SIN_BYTES);

    const int tid = threadIdx.x;
    const int b  = blockIdx.z;
    const int y0 = blockIdx.y * RT;
    const int x0 = blockIdx.x * TW;

    // ---- region 3 constant fill: {1.0 (K3), 0 (K7)} ----
    for (int i = tid; i < REG_ELEMS; i += 256)
        s_u2[3 * REG_STRIDE + i] = make_uint2(ONE_TF32, 0u);

    // ---- weight staging (small; divs fine) ----
    // zero tqq=3 entries (K3/K7): bias on tap 12 only
    for (int p = tid; p < 25 * 8; p += 256) {
        int tap = p >> 3, gg = p & 7;
        uint32_t bl = 0, bh = 0;
        if (tap == 12) { bl = cvt_tf32(bias[gg]); bh = cvt_tf32(bias[8 + gg]); }
        uint32_t* e = s_w2 + ((p * 4 + 3) * 4);
        e[0] = bl; e[1] = 0; e[2] = bh; e[3] = 0;
    }
    for (int i = tid; i < 25 * COUT * CIN; i += 256) {
        int tap = i / (COUT * CIN);
        int r   = i % (COUT * CIN);
        int co  = r / CIN;
        int ci  = r % CIN;
        int tqq  = ci >> 1;          // K = tqq + 4*(ci&1)
        int kodd = ci & 1;
        int gg   = co & 7;
        int half = co >> 3;
        s_w2[(((tap * 8 + gg) * 4 + tqq) * 4) + half * 2 + kodd] =
            cvt_tf32(g_Wd[(tap * CIN + ci) * COUT + co]);
    }

    // ---- input staging: contiguous STS.64 into regions 0..2 ----
    // main cols 0..63: thread (c = tid&63, rg = tid>>6) does rows rg+4k
    {
        const int c  = tid & 63;
        const int rg = tid >> 6;
        const int gx = x0 + c;
        const bool xok = gx < WIN;
        #pragma unroll
        for (int k = 0; k < 5; ++k) {
            const int r  = rg + 4 * k;
            const int gy = y0 + r;
            float2 v0 = make_float2(0.f, 0.f), v1 = v0, v2 = v0;
            if (xok && gy < HIN) {
                const float* ip = in + ((long long)(b * HIN + gy) * WIN + gx) * CIN;
                v0 = *(const float2*)(ip);
                v1 = *(const float2*)(ip + 2);
                v2 = *(const float2*)(ip + 4);
            }
            const int e = r * ACOLS + c;
            s_u2[e]                  = make_uint2(cvt_tf32(v0.x), cvt_tf32(v0.y));
            s_u2[REG_STRIDE + e]     = make_uint2(cvt_tf32(v1.x), cvt_tf32(v1.y));
            s_u2[2 * REG_STRIDE + e] = make_uint2(cvt_tf32(v2.x), cvt_tf32(v2.y));
        }
    }
    // halo cols 64..67: threads 0..79, one (c,r) each
    if (tid < 80) {
        const int c  = 64 + (tid & 3);
        const int r  = tid >> 2;
        const int gx = x0 + c;
        const int gy = y0 + r;
        float2 v0 = make_float2(0.f, 0.f), v1 = v0, v2 = v0;
        if (gx < WIN && gy < HIN) {
            const float* ip = in + ((long long)(b * HIN + gy) * WIN + gx) * CIN;
            v0 = *(const float2*)(ip);
            v1 = *(const float2*)(ip + 2);
            v2 = *(const float2*)(ip + 4);
        }
        const int e = r * ACOLS + c;
        s_u2[e]                  = make_uint2(cvt_tf32(v0.x), cvt_tf32(v0.y));
        s_u2[REG_STRIDE + e]     = make_uint2(cvt_tf32(v1.x), cvt_tf32(v1.y));
        s_u2[2 * REG_STRIDE + e] = make_uint2(cvt_tf32(v2.x), cvt_tf32(v2.y));
    }
    __syncthreads();

    // ---- per-warp MMA mainloop: 2 output rows, kx-outer ----
    const int w    = tid >> 5;
    const int lane = tid & 31;
    const int g    = lane >> 2;
    const int tq   = lane & 3;
    const int r0   = 2 * w;

    float d[2][8][4];
    #pragma unroll
    for (int rr = 0; rr < 2; ++rr)
        #pragma unroll
        for (int n = 0; n < 8; ++n)
            #pragma unroll
            for (int q = 0; q < 4; ++q) d[rr][n][q] = 0.f;

    uint4 aBuf[2][5];
    const uint32_t* wbase = s_w2 + (g * 4 + tq) * 4;
    const uint2* breg = s_u2 + tq * REG_STRIDE + g;   // + (row*ACOLS + n*8 + kx)

    #pragma unroll
    for (int sr = 0; sr < 6; ++sr) {
        const int cur = sr & 1;
        const int prv = cur ^ 1;
        if (sr <= 4) {
            #pragma unroll
            for (int kx = 0; kx < 5; ++kx)
                aBuf[cur][kx] = *(const uint4*)(wbase + (sr * 5 + kx) * 128);
        }
        const uint2* brow = breg + (r0 + sr) * ACOLS;
        #pragma unroll
        for (int kx = 0; kx < 5; ++kx) {
            const uint4 aC = aBuf[cur][kx];
            const uint4 aP = aBuf[prv][kx];
            #pragma unroll
            for (int n = 0; n < 8; ++n) {
                uint2 bv = brow[n * 8 + kx];
                if (sr <= 4)
                    mma_tf32(d[0][n], aC.x, aC.z, aC.y, aC.w, bv.x, bv.y);
                if (sr >= 1)
                    mma_tf32(d[1][n], aP.x, aP.z, aP.y, aP.w, bv.x, bv.y);
            }
        }
    }

    // ---- epilogue: D(m=co, n=px) -> out[...][px][co] (bias already in D) ----
    #pragma unroll
    for (int rr = 0; rr < 2; ++rr) {
        const int gy = y0 + r0 + rr;
        if (gy < HOUT) {
            float* orow = out + ((long long)(b * HOUT + gy) * WOUT) * COUT;
            #pragma unroll
            for (int n = 0; n < 8; ++n) {
                int px = x0 + n * 8 + 2 * tq;
                if (px < WOUT) {
                    float* p = orow + (long long)px * COUT;
                    p[g]     = d[rr][n][0];
                    p[g + 8] = d[rr][n][2];
                }
                if (px + 1 < WOUT) {
                    float* p = orow + (long long)(px + 1) * COUT;
                    p[g]     = d[rr][n][1];
                    p[g + 8] = d[rr][n][3];
                }
            }
        }
    }
}

extern "C" void kernel_launch(void* const* d_in, const int* in_sizes, int n_in,
                              void* d_out, int out_size) {
    const float* inputs = (const float*)d_in[0];
    const float* w3     = (const float*)d_in[1];
    const float* w4     = (const float*)d_in[2];
    const float* w44    = (const float*)d_in[3];
    const float* w6     = (const float*)d_in[4];
    const float* bias   = (const float*)d_in[5];

    cudaFuncSetAttribute(conv_mma_kernel,
                         cudaFuncAttributeMaxDynamicSharedMemorySize,
                         SMEM_BYTES);

    build_weights<<<(FS * FS * CIN * COUT + 255) / 256, 256>>>(w3, w4, w44, w6);

    dim3 grid((WOUT + TW - 1) / TW,   // 8
              (HOUT + RT - 1) / RT,   // 32
              BATCHN);                 // 32
    conv_mma_kernel<<<grid, 256, SMEM_BYTES>>>(inputs, bias, (float*)d_out);
}

// round 13
// speedup vs baseline: 1.1009x; 1.1009x over previous
#include <cuda_runtime.h>
#include <cstdint>

#define CIN   6
#define COUT  16
#define FS    5
#define HIN   512
#define WIN   512
#define HOUT  508
#define WOUT  508
#define BATCHN 32

// ---- dense weights (fp32), built per launch ----
__device__ float g_Wd[FS * FS * CIN * COUT];

__global__ void build_weights(const float* __restrict__ w3,
                              const float* __restrict__ w4,
                              const float* __restrict__ w44,
                              const float* __restrict__ w6) {
    int idx = blockIdx.x * blockDim.x + threadIdx.x;
    if (idx >= FS * FS * CIN * COUT) return;
    int co = idx % COUT;
    int ci = (idx / COUT) % CIN;
    int kk = idx / (COUT * CIN);
    float v = 0.f;
    if (co < 6) {
        int i = co;
        #pragma unroll
        for (int m = 0; m < 3; ++m)
            if (ci == (i + m) % 6) v = w3[(kk * 3 + m) * 6 + i];
    } else if (co < 12) {
        int k = co - 6;
        #pragma unroll
        for (int m = 0; m < 4; ++m)
            if (ci == (k + m) % 6) v = w4[(kk * 4 + m) * 6 + k];
    } else if (co < 15) {
        int k = co - 12;
        const int off[4] = {0, 1, 3, 4};
        #pragma unroll
        for (int m = 0; m < 4; ++m)
            if (ci == (k + off[m]) % 6) v = w44[(kk * 4 + m) * 3 + k];
    } else {
        v = w6[kk * 6 + ci];
    }
    g_Wd[idx] = v;
}

// ===== mma.sync tf32 conv, R11 layout + STS.128-contiguous staging =====
// smem s_in[row][col][8]: slot 2t = K t, slot 2t+1 = K t+4 (LDS.64 pair).
// ci→K: ci0→K0 ci1→K4 ci2→K1 ci3→K5 ci4→K2 ci5→K6; K3 = bias lane
// (input 1.0, weight bias on tap 12); K7 = 0. So slots 0..7 =
// {ci0,ci1,ci2,ci3,ci4,ci5,1.0,0} -> pixel stages as 2x STS.128.

#define TW    64
#define RT    16            // 8 warps x 2 rows
#define AROWS (RT + 4)      // 20
#define ACOLS (TW + 4)      // 68

#define SIN_BYTES  (AROWS * ACOLS * 8 * 4)   // 43520
#define SW_BYTES   (25 * 8 * 4 * 16)         // 12800
#define SMEM_BYTES (SIN_BYTES + SW_BYTES)

#define ONE_TF32 0x3F800000u

__device__ __forceinline__ uint32_t cvt_tf32(float f) {
    uint32_t u;
    asm("cvt.rna.tf32.f32 %0, %1;" : "=r"(u) : "f"(f));
    return u;
}

__device__ __forceinline__ void mma_tf32(float d[4],
                                         uint32_t a0, uint32_t a1,
                                         uint32_t a2, uint32_t a3,
                                         uint32_t b0, uint32_t b1) {
    asm volatile(
        "mma.sync.aligned.m16n8k8.row.col.f32.tf32.tf32.f32 "
        "{%0,%1,%2,%3}, {%4,%5,%6,%7}, {%8,%9}, {%0,%1,%2,%3};"
        : "+f"(d[0]), "+f"(d[1]), "+f"(d[2]), "+f"(d[3])
        : "r"(a0), "r"(a1), "r"(a2), "r"(a3), "r"(b0), "r"(b1));
}

__global__ __launch_bounds__(256, 2) void conv_mma_kernel(
    const float* __restrict__ in,
    const float* __restrict__ bias,
    float* __restrict__ out) {

    extern __shared__ char smem[];
    uint32_t (*s_in)[ACOLS][8] = (uint32_t(*)[ACOLS][8])smem;
    // s_w2[tap][gg][tqq] = uint4{(g,Ktqq),(g,Ktqq+4),(g+8,Ktqq),(g+8,Ktqq+4)}
    uint32_t* s_w2 = (uint32_t*)(smem + SIN_BYTES);

    const int tid = threadIdx.x;
    const int b  = blockIdx.z;
    const int y0 = blockIdx.y * RT;
    const int x0 = blockIdx.x * TW;

    // ---- weight staging ----
    // tqq=3 entries hold K3 (bias, tap 12 only) and K7 (zero)
    for (int p = tid; p < 25 * 8; p += 256) {
        int tap = p >> 3, gg = p & 7;
        uint32_t bl = 0, bh = 0;
        if (tap == 12) { bl = cvt_tf32(bias[gg]); bh = cvt_tf32(bias[8 + gg]); }
        uint32_t* e = s_w2 + ((p * 4 + 3) * 4);
        e[0] = bl; e[1] = 0; e[2] = bh; e[3] = 0;
    }
    for (int i = tid; i < 25 * COUT * CIN; i += 256) {
        int tap = i / (COUT * CIN);
        int r   = i % (COUT * CIN);
        int co  = r / CIN;
        int ci  = r % CIN;
        int tqq  = ci >> 1;          // K = tqq + 4*(ci&1)
        int kodd = ci & 1;
        int gg   = co & 7;
        int half = co >> 3;
        s_w2[(((tap * 8 + gg) * 4 + tqq) * 4) + half * 2 + kodd] =
            cvt_tf32(g_Wd[(tap * CIN + ci) * COUT + co]);
    }

    // ---- input staging: 2x STS.128 per pixel ----
    // main cols 0..63: thread (c = tid&63, rg = tid>>6) does rows rg+4k
    {
        const int c  = tid & 63;
        const int rg = tid >> 6;
        const int gx = x0 + c;
        const bool xok = gx < WIN;
        #pragma unroll
        for (int k = 0; k < 5; ++k) {
            const int r  = rg + 4 * k;
            const int gy = y0 + r;
            float2 v0 = make_float2(0.f, 0.f), v1 = v0, v2 = v0;
            if (xok && gy < HIN) {
                const float* ip = in + ((long long)(b * HIN + gy) * WIN + gx) * CIN;
                v0 = *(const float2*)(ip);
                v1 = *(const float2*)(ip + 2);
                v2 = *(const float2*)(ip + 4);
            }
            uint4* sp = (uint4*)&s_in[r][c][0];
            sp[0] = make_uint4(cvt_tf32(v0.x), cvt_tf32(v0.y),
                               cvt_tf32(v1.x), cvt_tf32(v1.y));
            sp[1] = make_uint4(cvt_tf32(v2.x), cvt_tf32(v2.y), ONE_TF32, 0u);
        }
    }
    // halo cols 64..67: threads 0..79, one (c,r) each
    if (tid < 80) {
        const int c  = 64 + (tid & 3);
        const int r  = tid >> 2;
        const int gx = x0 + c;
        const int gy = y0 + r;
        float2 v0 = make_float2(0.f, 0.f), v1 = v0, v2 = v0;
        if (gx < WIN && gy < HIN) {
            const float* ip = in + ((long long)(b * HIN + gy) * WIN + gx) * CIN;
            v0 = *(const float2*)(ip);
            v1 = *(const float2*)(ip + 2);
            v2 = *(const float2*)(ip + 4);
        }
        uint4* sp = (uint4*)&s_in[r][c][0];
        sp[0] = make_uint4(cvt_tf32(v0.x), cvt_tf32(v0.y),
                           cvt_tf32(v1.x), cvt_tf32(v1.y));
        sp[1] = make_uint4(cvt_tf32(v2.x), cvt_tf32(v2.y), ONE_TF32, 0u);
    }
    __syncthreads();

    // ---- per-warp MMA mainloop: 2 output rows, kx-outer (R10/R11) ----
    const int w    = tid >> 5;
    const int lane = tid & 31;
    const int g    = lane >> 2;
    const int tq   = lane & 3;
    const int r0   = 2 * w;

    float d[2][8][4];
    #pragma unroll
    for (int rr = 0; rr < 2; ++rr)
        #pragma unroll
        for (int n = 0; n < 8; ++n)
            #pragma unroll
            for (int q = 0; q < 4; ++q) d[rr][n][q] = 0.f;

    uint4 aBuf[2][5];
    const uint32_t* wbase = s_w2 + (g * 4 + tq) * 4;

    #pragma unroll
    for (int sr = 0; sr < 6; ++sr) {
        const int cur = sr & 1;
        const int prv = cur ^ 1;
        if (sr <= 4) {
            #pragma unroll
            for (int kx = 0; kx < 5; ++kx)
                aBuf[cur][kx] = *(const uint4*)(wbase + (sr * 5 + kx) * 128);
        }
        const uint32_t* brow = &s_in[r0 + sr][g][2 * tq];
        #pragma unroll
        for (int kx = 0; kx < 5; ++kx) {
            const uint4 aC = aBuf[cur][kx];
            const uint4 aP = aBuf[prv][kx];
            #pragma unroll
            for (int n = 0; n < 8; ++n) {
                uint2 bv = *(const uint2*)(brow + (n * 8 + kx) * 8);
                if (sr <= 4)
                    mma_tf32(d[0][n], aC.x, aC.z, aC.y, aC.w, bv.x, bv.y);
                if (sr >= 1)
                    mma_tf32(d[1][n], aP.x, aP.z, aP.y, aP.w, bv.x, bv.y);
            }
        }
    }

    // ---- epilogue: D(m=co, n=px) -> out[...][px][co] (bias already in D) ----
    #pragma unroll
    for (int rr = 0; rr < 2; ++rr) {
        const int gy = y0 + r0 + rr;
        if (gy < HOUT) {
            float* orow = out + ((long long)(b * HOUT + gy) * WOUT) * COUT;
            #pragma unroll
            for (int n = 0; n < 8; ++n) {
                int px = x0 + n * 8 + 2 * tq;
                if (px < WOUT) {
                    float* p = orow + (long long)px * COUT;
                    p[g]     = d[rr][n][0];
                    p[g + 8] = d[rr][n][2];
                }
                if (px + 1 < WOUT) {
                    float* p = orow + (long long)(px + 1) * COUT;
                    p[g]     = d[rr][n][1];
                    p[g + 8] = d[rr][n][3];
                }
            }
        }
    }
}

extern "C" void kernel_launch(void* const* d_in, const int* in_sizes, int n_in,
                              void* d_out, int out_size) {
    const float* inputs = (const float*)d_in[0];
    const float* w3     = (const float*)d_in[1];
    const float* w4     = (const float*)d_in[2];
    const float* w44    = (const float*)d_in[3];
    const float* w6     = (const float*)d_in[4];
    const float* bias   = (const float*)d_in[5];

    cudaFuncSetAttribute(conv_mma_kernel,
                         cudaFuncAttributeMaxDynamicSharedMemorySize,
                         SMEM_BYTES);

    build_weights<<<(FS * FS * CIN * COUT + 255) / 256, 256>>>(w3, w4, w44, w6);

    dim3 grid((WOUT + TW - 1) / TW,   // 8
              (HOUT + RT - 1) / RT,   // 32
              BATCHN);                 // 32
    conv_mma_kernel<<<grid, 256, SMEM_BYTES>>>(inputs, bias, (float*)d_out);
}

// round 14
// speedup vs baseline: 1.8469x; 1.6777x over previous
#include <cuda_runtime.h>
#include <cuda_fp16.h>
#include <cstdint>

#define CIN   6
#define COUT  16
#define FS    5
#define HIN   512
#define WIN   512
#define HOUT  508
#define WOUT  508
#define BATCHN 32

// ---- dense weights (fp32), built per launch ----
__device__ float g_Wd[FS * FS * CIN * COUT];

__global__ void build_weights(const float* __restrict__ w3,
                              const float* __restrict__ w4,
                              const float* __restrict__ w44,
                              const float* __restrict__ w6) {
    int idx = blockIdx.x * blockDim.x + threadIdx.x;
    if (idx >= FS * FS * CIN * COUT) return;
    int co = idx % COUT;
    int ci = (idx / COUT) % CIN;
    int kk = idx / (COUT * CIN);
    float v = 0.f;
    if (co < 6) {
        int i = co;
        #pragma unroll
        for (int m = 0; m < 3; ++m)
            if (ci == (i + m) % 6) v = w3[(kk * 3 + m) * 6 + i];
    } else if (co < 12) {
        int k = co - 6;
        #pragma unroll
        for (int m = 0; m < 4; ++m)
            if (ci == (k + m) % 6) v = w4[(kk * 4 + m) * 6 + k];
    } else if (co < 15) {
        int k = co - 12;
        const int off[4] = {0, 1, 3, 4};
        #pragma unroll
        for (int m = 0; m < 4; ++m)
            if (ci == (k + off[m]) % 6) v = w44[(kk * 4 + m) * 3 + k];
    } else {
        v = w6[kk * 6 + ci];
    }
    g_Wd[idx] = v;
}

// ===== fp16 mma.sync m16n8k16 conv, 2 rows/warp, 2-kx-packed K =====
// A = weights (m16 co x k16), B = input (k16 x n8 px), D = f32 co x px.
// K 0..7  = pixel at kx=2p : {ci0..ci5, biaslane(1.0), 0}
// K 8..15 = pixel at kx=2p+1: {ci0..ci5, 0, 0}   (p=2 upper half weights = 0)
// Weight K6 = bias[co] only on tap-pair (ky=2, p=1) (contains tap 12).
// Input pixel in smem = 16 B = uint4{h2(ci0,ci1),h2(ci2,ci3),h2(ci4,ci5),h2(1,0)}.
// B fragment: b0 = pixel(kx)   u32[tq]  (LDS.32, 1 wf)
//             b1 = pixel(kx+1) u32[tq]  (LDS.32, 1 wf)

#define TW    64
#define RT    16            // 8 warps x 2 rows
#define AROWS (RT + 4)      // 20
#define ACOLS (TW + 5)      // 69: extra col for the kx=5 read of pair p=2

__device__ __forceinline__ uint32_t h2(float a, float b) {
    __half2 h = __floats2half2_rn(a, b);
    return *(uint32_t*)&h;
}

__device__ __forceinline__ void mma_f16(float d[4],
                                        uint32_t a0, uint32_t a1,
                                        uint32_t a2, uint32_t a3,
                                        uint32_t b0, uint32_t b1) {
    asm volatile(
        "mma.sync.aligned.m16n8k16.row.col.f32.f16.f16.f32 "
        "{%0,%1,%2,%3}, {%4,%5,%6,%7}, {%8,%9}, {%0,%1,%2,%3};"
        : "+f"(d[0]), "+f"(d[1]), "+f"(d[2]), "+f"(d[3])
        : "r"(a0), "r"(a1), "r"(a2), "r"(a3), "r"(b0), "r"(b1));
}

__global__ __launch_bounds__(256, 2) void conv_mma_kernel(
    const float* __restrict__ in,
    const float* __restrict__ bias,
    float* __restrict__ out) {

    // s_in[row][col] = one pixel (uint4). s_w[kp][g][tq] = uint4 {a0,a1,a2,a3}.
    __shared__ uint4 s_in[AROWS][ACOLS];        // 22080 B
    __shared__ uint4 s_w[15][8][4];             // 7680 B

    const int tid = threadIdx.x;
    const int b  = blockIdx.z;
    const int y0 = blockIdx.y * RT;
    const int x0 = blockIdx.x * TW;

    // ---- weight staging: 480 uint4 entries ----
    for (int e = tid; e < 15 * 8 * 4; e += 256) {
        const int kp  = e >> 5;          // tap pair: ky*3 + p
        const int gg  = (e >> 2) & 7;
        const int tqq = e & 3;
        const int ky  = kp / 3;
        const int p   = kp - 3 * ky;
        float wv[2][4];                  // [co half][K of {2tqq,2tqq+1,2tqq+8,2tqq+9}]
        #pragma unroll
        for (int j = 0; j < 4; ++j) {
            const int K    = 2 * tqq + (j & 1) + (j >> 1) * 8;
            const int half = K >> 3;
            const int s    = K & 7;
            const int kx   = 2 * p + half;
            #pragma unroll
            for (int h = 0; h < 2; ++h) {
                const int co = gg + 8 * h;
                float v = 0.f;
                if (kx <= 4) {
                    if (s < 6)
                        v = g_Wd[((ky * 5 + kx) * 6 + s) * COUT + co];
                    else if (s == 6 && half == 0 && ky == 2 && p == 1)
                        v = bias[co];
                }
                wv[h][j] = v;
            }
        }
        s_w[kp][gg][tqq] = make_uint4(h2(wv[0][0], wv[0][1]),   // a0: co g,  K lo
                                      h2(wv[1][0], wv[1][1]),   // a1: co g+8,K lo
                                      h2(wv[0][2], wv[0][3]),   // a2: co g,  K hi
                                      h2(wv[1][2], wv[1][3]));  // a3: co g+8,K hi
    }

    // ---- input staging: 1x STS.128 per pixel ----
    {
        const int c  = tid & 63;
        const int rg = tid >> 6;
        const int gx = x0 + c;
        const bool xok = gx < WIN;
        #pragma unroll
        for (int k = 0; k < 5; ++k) {
            const int r  = rg + 4 * k;
            const int gy = y0 + r;
            float2 v0 = make_float2(0.f, 0.f), v1 = v0, v2 = v0;
            if (xok && gy < HIN) {
                const float* ip = in + ((long long)(b * HIN + gy) * WIN + gx) * CIN;
                v0 = *(const float2*)(ip);
                v1 = *(const float2*)(ip + 2);
                v2 = *(const float2*)(ip + 4);
            }
            s_in[r][c] = make_uint4(h2(v0.x, v0.y), h2(v1.x, v1.y),
                                    h2(v2.x, v2.y), h2(1.f, 0.f));
        }
    }
    // halo cols 64..68: threads 0..99
    if (tid < 100) {
        const int c  = 64 + tid / 20;
        const int r  = tid - 20 * (tid / 20);
        const int gx = x0 + c;
        const int gy = y0 + r;
        float2 v0 = make_float2(0.f, 0.f), v1 = v0, v2 = v0;
        if (gx < WIN && gy < HIN) {
            const float* ip = in + ((long long)(b * HIN + gy) * WIN + gx) * CIN;
            v0 = *(const float2*)(ip);
            v1 = *(const float2*)(ip + 2);
            v2 = *(const float2*)(ip + 4);
        }
        s_in[r][c] = make_uint4(h2(v0.x, v0.y), h2(v1.x, v1.y),
                                h2(v2.x, v2.y), h2(1.f, 0.f));
    }
    __syncthreads();

    // ---- per-warp MMA mainloop: 2 output rows, pair-outer ----
    const int w    = tid >> 5;
    const int lane = tid & 31;
    const int g    = lane >> 2;
    const int tq   = lane & 3;
    const int r0   = 2 * w;

    float d[2][8][4];
    #pragma unroll
    for (int rr = 0; rr < 2; ++rr)
        #pragma unroll
        for (int n = 0; n < 8; ++n)
            #pragma unroll
            for (int q = 0; q < 4; ++q) d[rr][n][q] = 0.f;

    uint4 aBuf[2][3];
    const uint32_t* s_inf = (const uint32_t*)&s_in[0][0];

    #pragma unroll
    for (int sr = 0; sr < 6; ++sr) {
        const int cur = sr & 1;
        const int prv = cur ^ 1;
        if (sr <= 4) {
            #pragma unroll
            for (int p = 0; p < 3; ++p)
                aBuf[cur][p] = s_w[sr * 3 + p][g][tq];
        }
        // base u32 ptr for this row: pixel (row*ACOLS + col), lane offset tq
        const uint32_t* brow = s_inf + ((r0 + sr) * ACOLS + g) * 4 + tq;
        #pragma unroll
        for (int p = 0; p < 3; ++p) {
            const uint4 aC = aBuf[cur][p];
            const uint4 aP = aBuf[prv][p];
            #pragma unroll
            for (int n = 0; n < 8; ++n) {
                const uint32_t* bp = brow + (n * 8 + 2 * p) * 4;
                uint32_t b0 = bp[0];     // pixel kx=2p
                uint32_t b1 = bp[4];     // pixel kx=2p+1
                if (sr <= 4)
                    mma_f16(d[0][n], aC.x, aC.y, aC.z, aC.w, b0, b1);
                if (sr >= 1)
                    mma_f16(d[1][n], aP.x, aP.y, aP.z, aP.w, b0, b1);
            }
        }
    }

    // ---- epilogue: D(m=co, n=px) -> out[...][px][co] (bias already in D) ----
    #pragma unroll
    for (int rr = 0; rr < 2; ++rr) {
        const int gy = y0 + r0 + rr;
        if (gy < HOUT) {
            float* orow = out + ((long long)(b * HOUT + gy) * WOUT) * COUT;
            #pragma unroll
            for (int n = 0; n < 8; ++n) {
                int px = x0 + n * 8 + 2 * tq;
                if (px < WOUT) {
                    float* p = orow + (long long)px * COUT;
                    p[g]     = d[rr][n][0];
                    p[g + 8] = d[rr][n][2];
                }
                if (px + 1 < WOUT) {
                    float* p = orow + (long long)(px + 1) * COUT;
                    p[g]     = d[rr][n][1];
                    p[g + 8] = d[rr][n][3];
                }
            }
        }
    }
}

extern "C" void kernel_launch(void* const* d_in, const int* in_sizes, int n_in,
                              void* d_out, int out_size) {
    const float* inputs = (const float*)d_in[0];
    const float* w3     = (const float*)d_in[1];
    const float* w4     = (const float*)d_in[2];
    const float* w44    = (const float*)d_in[3];
    const float* w6     = (const float*)d_in[4];
    const float* bias   = (const float*)d_in[5];

    build_weights<<<(FS * FS * CIN * COUT + 255) / 256, 256>>>(w3, w4, w44, w6);

    dim3 grid((WOUT + TW - 1) / TW,   // 8
              (HOUT + RT - 1) / RT,   // 32
              BATCHN);                 // 32
    conv_mma_kernel<<<grid, 256>>>(inputs, bias, (float*)d_out);
}

// round 15
// speedup vs baseline: 2.0157x; 1.0914x over previous
#include <cuda_runtime.h>
#include <cuda_fp16.h>
#include <cstdint>

#define CIN   6
#define COUT  16
#define FS    5
#define HIN   512
#define WIN   512
#define HOUT  508
#define WOUT  508
#define BATCHN 32

// ---- dense weights (fp32), built per launch ----
__device__ float g_Wd[FS * FS * CIN * COUT];

__global__ void build_weights(const float* __restrict__ w3,
                              const float* __restrict__ w4,
                              const float* __restrict__ w44,
                              const float* __restrict__ w6) {
    int idx = blockIdx.x * blockDim.x + threadIdx.x;
    if (idx >= FS * FS * CIN * COUT) return;
    int co = idx % COUT;
    int ci = (idx / COUT) % CIN;
    int kk = idx / (COUT * CIN);
    float v = 0.f;
    if (co < 6) {
        int i = co;
        #pragma unroll
        for (int m = 0; m < 3; ++m)
            if (ci == (i + m) % 6) v = w3[(kk * 3 + m) * 6 + i];
    } else if (co < 12) {
        int k = co - 6;
        #pragma unroll
        for (int m = 0; m < 4; ++m)
            if (ci == (k + m) % 6) v = w4[(kk * 4 + m) * 6 + k];
    } else if (co < 15) {
        int k = co - 12;
        const int off[4] = {0, 1, 3, 4};
        #pragma unroll
        for (int m = 0; m < 4; ++m)
            if (ci == (k + off[m]) % 6) v = w44[(kk * 4 + m) * 3 + k];
    } else {
        v = w6[kk * 6 + ci];
    }
    g_Wd[idx] = v;
}

// ===== fp16 mma m16n8k16 conv, permuted m/n for coalesced epilogue =====
// m-row g ↦ co 2g ; m-row g+8 ↦ co 2g+1  (lane's d0,d2 = consecutive co)
// n-col c ↦ px (c>>1)+4(c&1)             (tq lanes cover consecutive px)
// => D fragment stores as contiguous float2, 2 wf per STG.64.
// K 0..7 = pixel kx=2p {ci0..ci5, bias(1.0), 0}; K 8..15 = kx=2p+1.
// Weight K6 = bias[co] only on tap-pair (ky=2, p=1) (contains tap 12).

#define TW    64
#define RT    16            // 8 warps x 2 rows
#define AROWS (RT + 4)      // 20
#define ACOLS (TW + 5)      // 69

__device__ __forceinline__ uint32_t h2(float a, float b) {
    __half2 h = __floats2half2_rn(a, b);
    return *(uint32_t*)&h;
}

__device__ __forceinline__ void mma_f16(float d[4],
                                        uint32_t a0, uint32_t a1,
                                        uint32_t a2, uint32_t a3,
                                        uint32_t b0, uint32_t b1) {
    asm volatile(
        "mma.sync.aligned.m16n8k16.row.col.f32.f16.f16.f32 "
        "{%0,%1,%2,%3}, {%4,%5,%6,%7}, {%8,%9}, {%0,%1,%2,%3};"
        : "+f"(d[0]), "+f"(d[1]), "+f"(d[2]), "+f"(d[3])
        : "r"(a0), "r"(a1), "r"(a2), "r"(a3), "r"(b0), "r"(b1));
}

__global__ __launch_bounds__(256, 2) void conv_mma_kernel(
    const float* __restrict__ in,
    const float* __restrict__ bias,
    float* __restrict__ out) {

    __shared__ uint4 s_in[AROWS][ACOLS];        // 22080 B
    __shared__ uint4 s_w[15][8][4];             // 7680 B

    const int tid = threadIdx.x;
    const int b  = blockIdx.z;
    const int y0 = blockIdx.y * RT;
    const int x0 = blockIdx.x * TW;

    // ---- weight staging: 480 uint4 entries; m-row -> co permuted ----
    for (int e = tid; e < 15 * 8 * 4; e += 256) {
        const int kp  = e >> 5;          // tap pair: ky*3 + p
        const int gg  = (e >> 2) & 7;
        const int tqq = e & 3;
        const int ky  = kp / 3;
        const int p   = kp - 3 * ky;
        float wv[2][4];                  // [h: m-row half][K of {2tqq,2tqq+1,2tqq+8,2tqq+9}]
        #pragma unroll
        for (int j = 0; j < 4; ++j) {
            const int K    = 2 * tqq + (j & 1) + (j >> 1) * 8;
            const int half = K >> 3;
            const int s    = K & 7;
            const int kx   = 2 * p + half;
            #pragma unroll
            for (int h = 0; h < 2; ++h) {
                const int co = 2 * gg + h;   // PERMUTED: m-row g -> co 2g, g+8 -> 2g+1
                float v = 0.f;
                if (kx <= 4) {
                    if (s < 6)
                        v = g_Wd[((ky * 5 + kx) * 6 + s) * COUT + co];
                    else if (s == 6 && half == 0 && ky == 2 && p == 1)
                        v = bias[co];
                }
                wv[h][j] = v;
            }
        }
        s_w[kp][gg][tqq] = make_uint4(h2(wv[0][0], wv[0][1]),   // a0: m g,   K lo
                                      h2(wv[1][0], wv[1][1]),   // a1: m g+8, K lo
                                      h2(wv[0][2], wv[0][3]),   // a2: m g,   K hi
                                      h2(wv[1][2], wv[1][3]));  // a3: m g+8, K hi
    }

    // ---- input staging: 1x STS.128 per pixel ----
    {
        const int c  = tid & 63;
        const int rg = tid >> 6;
        const int gx = x0 + c;
        const bool xok = gx < WIN;
        #pragma unroll
        for (int k = 0; k < 5; ++k) {
            const int r  = rg + 4 * k;
            const int gy = y0 + r;
            float2 v0 = make_float2(0.f, 0.f), v1 = v0, v2 = v0;
            if (xok && gy < HIN) {
                const float* ip = in + ((long long)(b * HIN + gy) * WIN + gx) * CIN;
                v0 = *(const float2*)(ip);
                v1 = *(const float2*)(ip + 2);
                v2 = *(const float2*)(ip + 4);
            }
            s_in[r][c] = make_uint4(h2(v0.x, v0.y), h2(v1.x, v1.y),
                                    h2(v2.x, v2.y), h2(1.f, 0.f));
        }
    }
    // halo cols 64..68: threads 0..99
    if (tid < 100) {
        const int c  = 64 + tid / 20;
        const int r  = tid - 20 * (tid / 20);
        const int gx = x0 + c;
        const int gy = y0 + r;
        float2 v0 = make_float2(0.f, 0.f), v1 = v0, v2 = v0;
        if (gx < WIN && gy < HIN) {
            const float* ip = in + ((long long)(b * HIN + gy) * WIN + gx) * CIN;
            v0 = *(const float2*)(ip);
            v1 = *(const float2*)(ip + 2);
            v2 = *(const float2*)(ip + 4);
        }
        s_in[r][c] = make_uint4(h2(v0.x, v0.y), h2(v1.x, v1.y),
                                h2(v2.x, v2.y), h2(1.f, 0.f));
    }
    __syncthreads();

    // ---- per-warp MMA mainloop: 2 output rows, pair-outer ----
    const int w    = tid >> 5;
    const int lane = tid & 31;
    const int g    = lane >> 2;
    const int tq   = lane & 3;
    const int r0   = 2 * w;
    const int pxg  = (g >> 1) + 4 * (g & 1);   // PERMUTED n-col -> px offset

    float d[2][8][4];
    #pragma unroll
    for (int rr = 0; rr < 2; ++rr)
        #pragma unroll
        for (int n = 0; n < 8; ++n)
            #pragma unroll
            for (int q = 0; q < 4; ++q) d[rr][n][q] = 0.f;

    uint4 aBuf[2][3];
    const uint32_t* s_inf = (const uint32_t*)&s_in[0][0];

    #pragma unroll
    for (int sr = 0; sr < 6; ++sr) {
        const int cur = sr & 1;
        const int prv = cur ^ 1;
        if (sr <= 4) {
            #pragma unroll
            for (int p = 0; p < 3; ++p)
                aBuf[cur][p] = s_w[sr * 3 + p][g][tq];
        }
        const uint32_t* brow = s_inf + ((r0 + sr) * ACOLS + pxg) * 4 + tq;
        #pragma unroll
        for (int p = 0; p < 3; ++p) {
            const uint4 aC = aBuf[cur][p];
            const uint4 aP = aBuf[prv][p];
            #pragma unroll
            for (int n = 0; n < 8; ++n) {
                const uint32_t* bp = brow + (n * 8 + 2 * p) * 4;
                uint32_t b0 = bp[0];     // pixel kx=2p
                uint32_t b1 = bp[4];     // pixel kx=2p+1
                if (sr <= 4)
                    mma_f16(d[0][n], aC.x, aC.y, aC.z, aC.w, b0, b1);
                if (sr >= 1)
                    mma_f16(d[1][n], aP.x, aP.y, aP.z, aP.w, b0, b1);
            }
        }
    }

    // ---- epilogue: coalesced float2 stores (co pairs, consecutive px) ----
    // lane (g,tq): d0,d2 = (co 2g,2g+1, px n8+tq) ; d1,d3 = (.., px n8+4+tq)
    #pragma unroll
    for (int rr = 0; rr < 2; ++rr) {
        const int gy = y0 + r0 + rr;
        if (gy < HOUT) {
            float* orow = out + ((long long)(b * HOUT + gy) * WOUT) * COUT;
            #pragma unroll
            for (int n = 0; n < 8; ++n) {
                int pxA = x0 + n * 8 + tq;
                int pxB = pxA + 4;
                if (pxA < WOUT)
                    *(float2*)(orow + (long long)pxA * COUT + 2 * g) =
                        make_float2(d[rr][n][0], d[rr][n][2]);
                if (pxB < WOUT)
                    *(float2*)(orow + (long long)pxB * COUT + 2 * g) =
                        make_float2(d[rr][n][1], d[rr][n][3]);
            }
        }
    }
}

extern "C" void kernel_launch(void* const* d_in, const int* in_sizes, int n_in,
                              void* d_out, int out_size) {
    const float* inputs = (const float*)d_in[0];
    const float* w3     = (const float*)d_in[1];
    const float* w4     = (const float*)d_in[2];
    const float* w44    = (const float*)d_in[3];
    const float* w6     = (const float*)d_in[4];
    const float* bias   = (const float*)d_in[5];

    build_weights<<<(FS * FS * CIN * COUT + 255) / 256, 256>>>(w3, w4, w44, w6);

    dim3 grid((WOUT + TW - 1) / TW,   // 8
              (HOUT + RT - 1) / RT,   // 32
              BATCHN);                 // 32
    conv_mma_kernel<<<grid, 256>>>(inputs, bias, (float*)d_out);
}